// round 10
// baseline (speedup 1.0000x reference)
#include <cuda_runtime.h>
#include <cuda_bf16.h>

// TopKPool: single kernel, 4 logical phases for temporal stagger.
//   512 blocks x 256 threads (proven 6.1 TB/s stream config). Each block runs 4
//   sequential tasks of 32 K-rows, row-major: batch rows finish in 4 waves at
//   ~25/50/75/100% of the stream. The block completing a row's 16th task runs
//   that row's tail (top-k + indicators + pooling) inline — phases 1-3 tails
//   execute UNDER the ongoing stream; only phase 4's 32 tails are exposed.
//   Fences are per-task (4/block over 33us), not per-50KB like the R8 failure.
// Output layout: [pooled (B*D) | attn_weights (B*K)], fp32.

#define NEG_INF  (-1e30f)
#define SENTINEL (-2e30f)

constexpr int Bv = 128;
constexpr int Kv = 512;
constexpr int Dv = 768;
constexpr int D4 = Dv / 4;            // 192 float4 per row
constexpr int MAX_TOPK = 64;

constexpr int TROWS   = 32;           // K-rows per task
constexpr int TPR     = Kv / TROWS;   // 16 tasks per batch row
constexpr int GRID    = 512;          // all resident (3.46/SM)
constexpr int PHASES  = 4;            // tasks per block
constexpr int T       = 256;          // 8 warps

__device__ float g_scores[Bv * Kv];   // 256 KB scratch (L2-resident)
__device__ int   g_count[Bv];         // zero-init; self-resetting per launch

__device__ __forceinline__ int clamp_ksel(int k) {
    if (k < 1) k = 1;
    if (k > MAX_TOPK) k = MAX_TOPK;
    return k;
}

__global__ __launch_bounds__(T)
void topkpool_phased(const float* __restrict__ emb,
                     const int*   __restrict__ mask,
                     const float* __restrict__ w,
                     const float* __restrict__ bias,
                     const int*   __restrict__ topk,
                     float*       __restrict__ out)
{
    __shared__ int s_top[MAX_TOPK];
    __shared__ int s_last;

    const int tid  = threadIdx.x;
    const int lane = tid & 31;
    const int wid  = tid >> 5;

    float* out_pool = out;                      // (B, D)
    float* out_attn = out + (size_t)Bv * Dv;    // (B, K)

    // loop-invariant: scorer weight in registers (6 float4, lane-strided)
    const float4* wg = (const float4*)w;
    const float4 w0 = __ldg(&wg[  0 + lane]);
    const float4 w1 = __ldg(&wg[ 32 + lane]);
    const float4 w2 = __ldg(&wg[ 64 + lane]);
    const float4 w3 = __ldg(&wg[ 96 + lane]);
    const float4 w4 = __ldg(&wg[128 + lane]);
    const float4 w5 = __ldg(&wg[160 + lane]);
    const float  bval = __ldg(&bias[0]);
    const int    ksel = clamp_ksel(__ldg(&topk[0]));
    const float  inv  = 1.f / (float)ksel;

    #pragma unroll 1
    for (int p = 0; p < PHASES; p++) {
        const int t  = p * GRID + blockIdx.x;   // task id, row-major
        const int b  = t / TPR;                 // batch row
        const int k0 = (t % TPR) * TROWS;       // K-row base of this task

        const float* eb = emb + (size_t)b * Kv * Dv;

        // ---- stream 32 K-rows: 8 warps x 2 iters x 2 rows ----
        #pragma unroll 1
        for (int kk = wid; kk < TROWS / 2; kk += 8) {
            const int ka = k0 + kk;
            const int kb = k0 + kk + TROWS / 2;
            const float4* ra = (const float4*)(eb + (size_t)ka * Dv);
            const float4* rb = (const float4*)(eb + (size_t)kb * Dv);

            float4 a0 = __ldcs(&ra[  0 + lane]);
            float4 a1 = __ldcs(&ra[ 32 + lane]);
            float4 a2 = __ldcs(&ra[ 64 + lane]);
            float4 a3 = __ldcs(&ra[ 96 + lane]);
            float4 a4 = __ldcs(&ra[128 + lane]);
            float4 a5 = __ldcs(&ra[160 + lane]);
            float4 b0 = __ldcs(&rb[  0 + lane]);
            float4 b1 = __ldcs(&rb[ 32 + lane]);
            float4 b2 = __ldcs(&rb[ 64 + lane]);
            float4 b3 = __ldcs(&rb[ 96 + lane]);
            float4 b4 = __ldcs(&rb[128 + lane]);
            float4 b5 = __ldcs(&rb[160 + lane]);

            float acc_a = a0.x*w0.x + a0.y*w0.y + a0.z*w0.z + a0.w*w0.w
                        + a1.x*w1.x + a1.y*w1.y + a1.z*w1.z + a1.w*w1.w
                        + a2.x*w2.x + a2.y*w2.y + a2.z*w2.z + a2.w*w2.w
                        + a3.x*w3.x + a3.y*w3.y + a3.z*w3.z + a3.w*w3.w
                        + a4.x*w4.x + a4.y*w4.y + a4.z*w4.z + a4.w*w4.w
                        + a5.x*w5.x + a5.y*w5.y + a5.z*w5.z + a5.w*w5.w;
            float acc_b = b0.x*w0.x + b0.y*w0.y + b0.z*w0.z + b0.w*w0.w
                        + b1.x*w1.x + b1.y*w1.y + b1.z*w1.z + b1.w*w1.w
                        + b2.x*w2.x + b2.y*w2.y + b2.z*w2.z + b2.w*w2.w
                        + b3.x*w3.x + b3.y*w3.y + b3.z*w3.z + b3.w*w3.w
                        + b4.x*w4.x + b4.y*w4.y + b4.z*w4.z + b4.w*w4.w
                        + b5.x*w5.x + b5.y*w5.y + b5.z*w5.z + b5.w*w5.w;

            #pragma unroll
            for (int off = 16; off; off >>= 1) {
                acc_a += __shfl_xor_sync(0xFFFFFFFFu, acc_a, off);
                acc_b += __shfl_xor_sync(0xFFFFFFFFu, acc_b, off);
            }
            if (lane == 0) {
                float sa = acc_a + bval;
                float sb = acc_b + bval;
                if (__ldg(&mask[(size_t)b * Kv + ka]) == 0) sa = NEG_INF;
                if (__ldg(&mask[(size_t)b * Kv + kb]) == 0) sb = NEG_INF;
                g_scores[(size_t)b * Kv + ka] = sa;   // normal store -> L2
                g_scores[(size_t)b * Kv + kb] = sb;
            }
        }

        // zero this task's chunk of the attn row (d_out is poisoned)
        if (tid < TROWS)
            out_attn[(size_t)b * Kv + k0 + tid] = 0.f;

        // ---- completion: last of the row's 16 tasks runs the tail ----
        __threadfence();
        __syncthreads();
        if (tid == 0) {
            int old = atomicAdd(&g_count[b], 1);
            s_last = (old == TPR - 1);
        }
        __syncthreads();

        if (s_last) {
            if (wid == 0) {
                // warp 0: register tournament over all 512 scores (L2-hot)
                float v[16];
                const float* sc = g_scores + (size_t)b * Kv;
                #pragma unroll
                for (int j = 0; j < 16; j++) v[j] = __ldcg(&sc[lane + 32 * j]);

                for (int m = 0; m < ksel; m++) {
                    float bv = v[0]; int bj = 0;
                    #pragma unroll
                    for (int j = 1; j < 16; j++)
                        if (v[j] > bv) { bv = v[j]; bj = j; }   // ties: lowest j
                    int bidx = lane + 32 * bj;
                    #pragma unroll
                    for (int off = 16; off; off >>= 1) {
                        float v2 = __shfl_xor_sync(0xFFFFFFFFu, bv, off);
                        int   i2 = __shfl_xor_sync(0xFFFFFFFFu, bidx, off);
                        if (v2 > bv || (v2 == bv && i2 < bidx)) { bv = v2; bidx = i2; }
                    }
                    if (lane == (bidx & 31)) v[bidx >> 5] = SENTINEL;
                    if (lane == 0) s_top[m] = bidx;
                }
                if (lane == 0) g_count[b] = 0;      // reset for next replay
            }
            __syncthreads();

            if (tid < ksel)
                out_attn[(size_t)b * Kv + s_top[tid]] = inv;   // row fully zeroed

            // pooling: 192 threads, one float4 column each
            if (tid < D4) {
                const float4* ebv = (const float4*)eb;
                float4 sum = make_float4(0.f, 0.f, 0.f, 0.f);
                if (ksel == 8) {
                    int ix[8];
                    #pragma unroll
                    for (int m = 0; m < 8; m++) ix[m] = s_top[m];
                    #pragma unroll
                    for (int m = 0; m < 8; m++) {
                        float4 e = __ldg(&ebv[(size_t)ix[m] * D4 + tid]);
                        sum.x += e.x; sum.y += e.y; sum.z += e.z; sum.w += e.w;
                    }
                } else {
                    #pragma unroll 4
                    for (int m = 0; m < ksel; m++) {
                        float4 e = __ldg(&ebv[(size_t)s_top[m] * D4 + tid]);
                        sum.x += e.x; sum.y += e.y; sum.z += e.z; sum.w += e.w;
                    }
                }
                float4 r = make_float4(sum.x * inv, sum.y * inv,
                                       sum.z * inv, sum.w * inv);
                ((float4*)(out_pool + (size_t)b * Dv))[tid] = r;
            }
            // no extra barrier needed: next phase's s_top writes happen only
            // after that phase's fence+__syncthreads sequence
        }
    }
}

extern "C" void kernel_launch(void* const* d_in, const int* in_sizes, int n_in,
                              void* d_out, int out_size)
{
    const float* emb  = (const float*)d_in[0];
    const int*   mask = (const int*)  d_in[1];
    const float* w    = (const float*)d_in[2];
    const float* bias = (const float*)d_in[3];
    const int*   topk = (const int*)  d_in[4];
    float*       out  = (float*)d_out;
    (void)in_sizes; (void)n_in; (void)out_size;

    topkpool_phased<<<GRID, T>>>(emb, mask, w, bias, topk, out);
}

// round 11
// speedup vs baseline: 1.3109x; 1.3109x over previous
#include <cuda_runtime.h>
#include <cuda_bf16.h>

// TopKPool, 2 kernels with PDL:
//   K1: masked linear scores (201 MB stream @ ~6.1 TB/s, at BW floor),
//       per-segment top-ksel candidates as packed u64 keys, attn zeroing.
//   K2: 512 blocks (4 per batch row). Each block redundantly merges the row's
//       32 candidate keys (1 warp, L2-hot after PDL) and gathers only its
//       48-of-192 float4 column slice — 384 LDG.128/block instead of 1536,
//       breaking the single-block-per-SM LDG issue serialization seen in R7/R9.
// Output layout: [pooled (B*D) | attn_weights (B*K)], fp32.

#define NEG_INF  (-1e30f)

constexpr int Bv = 128;
constexpr int Kv = 512;
constexpr int Dv = 768;
constexpr int D4 = Dv / 4;            // 192 float4 per row
constexpr int MAX_TOPK = 64;

constexpr int SPLIT = 4;              // K-segments per batch row (K1)
constexpr int KSEG  = Kv / SPLIT;     // 128 rows per K1 block
constexpr int T1    = 256;            // 8 warps
constexpr int QS    = 4;              // column quarters per row (K2)
constexpr int CQ    = D4 / QS;        // 48 float4 columns per K2 block
constexpr int T2    = 128;            // 4 warps

// packed candidates: key = (orderable(score) << 32) | ~idx   (max-key = best)
__device__ unsigned long long g_cand[Bv * SPLIT * MAX_TOPK];

__device__ __forceinline__ int clamp_ksel(int k) {
    if (k < 1) k = 1;
    if (k > MAX_TOPK) k = MAX_TOPK;
    return k;
}

__device__ __forceinline__ unsigned long long pack_key(float v, int idx) {
    unsigned u = __float_as_uint(v);
    u = (u & 0x80000000u) ? ~u : (u | 0x80000000u);   // order-preserving map
    return ((unsigned long long)u << 32) | (unsigned)(~idx);   // tie -> lower idx
}

// ---------------- K1: scoring + per-segment top-k (unchanged, proven) ----------------
__global__ __launch_bounds__(T1)
void score_kernel(const float* __restrict__ emb,
                  const int*   __restrict__ mask,
                  const float* __restrict__ w,
                  const float* __restrict__ bias,
                  const int*   __restrict__ topk,
                  float*       __restrict__ out)
{
#if __CUDA_ARCH__ >= 900
    cudaTriggerProgrammaticLaunchCompletion();    // let K2 launch early
#endif
    __shared__ float s_sc[KSEG];

    const int tid  = threadIdx.x;
    const int lane = tid & 31;
    const int wid  = tid >> 5;

    const int b   = blockIdx.x >> 2;
    const int seg = blockIdx.x & 3;
    const int k0  = seg * KSEG;

    const float4* wg = (const float4*)w;
    const float4 w0 = __ldg(&wg[  0 + lane]);
    const float4 w1 = __ldg(&wg[ 32 + lane]);
    const float4 w2 = __ldg(&wg[ 64 + lane]);
    const float4 w3 = __ldg(&wg[ 96 + lane]);
    const float4 w4 = __ldg(&wg[128 + lane]);
    const float4 w5 = __ldg(&wg[160 + lane]);

    const float  bval = __ldg(&bias[0]);
    const float* eb   = emb + (size_t)b * Kv * Dv;

    float* out_attn = out + (size_t)Bv * Dv;

    for (int kk = wid; kk < KSEG / 2; kk += 8) {
        const int ka = kk;
        const int kb = kk + KSEG / 2;
        const float4* ra = (const float4*)(eb + (size_t)(k0 + ka) * Dv);
        const float4* rb = (const float4*)(eb + (size_t)(k0 + kb) * Dv);

        float4 a0 = __ldcs(&ra[  0 + lane]);
        float4 a1 = __ldcs(&ra[ 32 + lane]);
        float4 a2 = __ldcs(&ra[ 64 + lane]);
        float4 a3 = __ldcs(&ra[ 96 + lane]);
        float4 a4 = __ldcs(&ra[128 + lane]);
        float4 a5 = __ldcs(&ra[160 + lane]);
        float4 b0 = __ldcs(&rb[  0 + lane]);
        float4 b1 = __ldcs(&rb[ 32 + lane]);
        float4 b2 = __ldcs(&rb[ 64 + lane]);
        float4 b3 = __ldcs(&rb[ 96 + lane]);
        float4 b4 = __ldcs(&rb[128 + lane]);
        float4 b5 = __ldcs(&rb[160 + lane]);

        float acc_a = a0.x*w0.x + a0.y*w0.y + a0.z*w0.z + a0.w*w0.w
                    + a1.x*w1.x + a1.y*w1.y + a1.z*w1.z + a1.w*w1.w
                    + a2.x*w2.x + a2.y*w2.y + a2.z*w2.z + a2.w*w2.w
                    + a3.x*w3.x + a3.y*w3.y + a3.z*w3.z + a3.w*w3.w
                    + a4.x*w4.x + a4.y*w4.y + a4.z*w4.z + a4.w*w4.w
                    + a5.x*w5.x + a5.y*w5.y + a5.z*w5.z + a5.w*w5.w;
        float acc_b = b0.x*w0.x + b0.y*w0.y + b0.z*w0.z + b0.w*w0.w
                    + b1.x*w1.x + b1.y*w1.y + b1.z*w1.z + b1.w*w1.w
                    + b2.x*w2.x + b2.y*w2.y + b2.z*w2.z + b2.w*w2.w
                    + b3.x*w3.x + b3.y*w3.y + b3.z*w3.z + b3.w*w3.w
                    + b4.x*w4.x + b4.y*w4.y + b4.z*w4.z + b4.w*w4.w
                    + b5.x*w5.x + b5.y*w5.y + b5.z*w5.z + b5.w*w5.w;

        #pragma unroll
        for (int off = 16; off; off >>= 1) {
            acc_a += __shfl_xor_sync(0xFFFFFFFFu, acc_a, off);
            acc_b += __shfl_xor_sync(0xFFFFFFFFu, acc_b, off);
        }
        if (lane == 0) {
            float sa = acc_a + bval;
            float sb = acc_b + bval;
            if (__ldg(&mask[(size_t)b * Kv + k0 + ka]) == 0) sa = NEG_INF;
            if (__ldg(&mask[(size_t)b * Kv + k0 + kb]) == 0) sb = NEG_INF;
            s_sc[ka] = sa;
            s_sc[kb] = sb;
        }
    }

    // zero this block's chunk of the attn row (d_out is poisoned)
    for (int i = tid; i < KSEG; i += T1)
        out_attn[(size_t)b * Kv + k0 + i] = 0.f;

    __syncthreads();

    // per-segment top-ksel: tournament on packed u64 keys (warp 0)
    if (wid == 0) {
        int ksel = clamp_ksel(__ldg(&topk[0]));

        unsigned long long key[4];
        #pragma unroll
        for (int j = 0; j < 4; j++)
            key[j] = pack_key(s_sc[lane + 32 * j], k0 + lane + 32 * j);

        unsigned long long* cd = g_cand + (size_t)(b * SPLIT + seg) * MAX_TOPK;

        for (int m = 0; m < ksel; m++) {
            unsigned long long best = key[0];
            #pragma unroll
            for (int j = 1; j < 4; j++) if (key[j] > best) best = key[j];
            #pragma unroll
            for (int off = 16; off; off >>= 1) {
                unsigned long long o = __shfl_xor_sync(0xFFFFFFFFu, best, off);
                if (o > best) best = o;
            }
            #pragma unroll
            for (int j = 0; j < 4; j++) if (key[j] == best) key[j] = 0ull;
            if (lane == 0) cd[m] = best;
        }
    }
}

// ---------------- K2: 4 blocks per row, redundant merge + sliced gather ----------------
__global__ __launch_bounds__(T2)
void finish_kernel(const float* __restrict__ emb,
                   const int*   __restrict__ topk,
                   float*       __restrict__ out)
{
    __shared__ int s_gk[MAX_TOPK];

    const int b    = blockIdx.x >> 2;            // batch row
    const int q    = blockIdx.x & 3;             // column quarter
    const int tid  = threadIdx.x;
    const int lane = tid & 31;
    const int wid  = tid >> 5;

    // ---- preamble (independent of K1; runs during K1's tail under PDL) ----
    const int ksel = clamp_ksel(__ldg(&topk[0]));
    const int C    = SPLIT * ksel;
    const float inv = 1.f / (float)ksel;

    float* out_pool = out;                       // (B, D)
    float* out_attn = out + (size_t)Bv * Dv;     // (B, K)
    const float4* ebv = (const float4*)(emb + (size_t)b * Kv * Dv);
    const unsigned long long* cd = g_cand + (size_t)b * SPLIT * MAX_TOPK;

#if __CUDA_ARCH__ >= 900
    cudaGridDependencySynchronize();             // wait for K1 (memory visible)
#endif

    // ---- redundant merge (warp 0): u64 max tournament over C candidates ----
    if (wid == 0) {
        if (C <= 32) {
            unsigned long long key = 0ull;
            if (lane < C) {
                int sg = lane / ksel, m = lane - sg * ksel;
                key = __ldcg(&cd[(size_t)sg * MAX_TOPK + m]);
            }
            for (int m = 0; m < ksel; m++) {
                unsigned long long best = key;
                #pragma unroll
                for (int off = 16; off; off >>= 1) {
                    unsigned long long o = __shfl_xor_sync(0xFFFFFFFFu, best, off);
                    if (o > best) best = o;
                }
                if (key == best) key = 0ull;
                if (lane == 0) s_gk[m] = (int)(~(unsigned)(best & 0xFFFFFFFFull));
            }
        } else {
            unsigned long long key[8];
            #pragma unroll
            for (int j = 0; j < 8; j++) {
                int n = lane + 32 * j;
                if (n < C) {
                    int sg = n / ksel, m = n - sg * ksel;
                    key[j] = __ldcg(&cd[(size_t)sg * MAX_TOPK + m]);
                } else key[j] = 0ull;
            }
            for (int m = 0; m < ksel; m++) {
                unsigned long long best = key[0];
                #pragma unroll
                for (int j = 1; j < 8; j++) if (key[j] > best) best = key[j];
                #pragma unroll
                for (int off = 16; off; off >>= 1) {
                    unsigned long long o = __shfl_xor_sync(0xFFFFFFFFu, best, off);
                    if (o > best) best = o;
                }
                #pragma unroll
                for (int j = 0; j < 8; j++) if (key[j] == best) key[j] = 0ull;
                if (lane == 0) s_gk[m] = (int)(~(unsigned)(best & 0xFFFFFFFFull));
            }
        }
    }
    __syncthreads();

    // indicators: only quarter 0 writes (row zeroed by K1)
    if (q == 0 && tid < ksel)
        out_attn[(size_t)b * Kv + s_gk[tid]] = inv;

    // sliced gather: this block owns float4 columns [q*CQ, (q+1)*CQ)
    if (tid < CQ) {
        const int col = q * CQ + tid;
        float4 sum = make_float4(0.f, 0.f, 0.f, 0.f);
        if (ksel == 8) {
            int ix[8];
            #pragma unroll
            for (int m = 0; m < 8; m++) ix[m] = s_gk[m];
            #pragma unroll
            for (int m = 0; m < 8; m++) {
                float4 e = __ldg(&ebv[(size_t)ix[m] * D4 + col]);
                sum.x += e.x; sum.y += e.y; sum.z += e.z; sum.w += e.w;
            }
        } else {
            #pragma unroll 4
            for (int m = 0; m < ksel; m++) {
                float4 e = __ldg(&ebv[(size_t)s_gk[m] * D4 + col]);
                sum.x += e.x; sum.y += e.y; sum.z += e.z; sum.w += e.w;
            }
        }
        float4 r = make_float4(sum.x * inv, sum.y * inv, sum.z * inv, sum.w * inv);
        ((float4*)(out_pool + (size_t)b * Dv))[col] = r;
    }
}

extern "C" void kernel_launch(void* const* d_in, const int* in_sizes, int n_in,
                              void* d_out, int out_size)
{
    const float* emb  = (const float*)d_in[0];
    const int*   mask = (const int*)  d_in[1];
    const float* w    = (const float*)d_in[2];
    const float* bias = (const float*)d_in[3];
    const int*   topk = (const int*)  d_in[4];
    float*       out  = (float*)d_out;
    (void)in_sizes; (void)n_in; (void)out_size;

    score_kernel<<<Bv * SPLIT, T1>>>(emb, mask, w, bias, topk, out);

    // K2 with programmatic dependent launch: overlaps launch+preamble with K1 tail
    cudaLaunchConfig_t cfg = {};
    cfg.gridDim  = dim3(Bv * QS, 1, 1);
    cfg.blockDim = dim3(T2, 1, 1);
    cfg.dynamicSmemBytes = 0;
    cfg.stream = 0;
    cudaLaunchAttribute attrs[1];
    attrs[0].id = cudaLaunchAttributeProgrammaticStreamSerialization;
    attrs[0].val.programmaticStreamSerializationAllowed = 1;
    cfg.attrs = attrs;
    cfg.numAttrs = 1;
    cudaError_t err = cudaLaunchKernelEx(&cfg, finish_kernel, emb, topk, out);
    if (err != cudaSuccess) {
        finish_kernel<<<Bv * QS, T2>>>(emb, topk, out);
    }
}